// round 13
// baseline (speedup 1.0000x reference)
#include <cuda_runtime.h>
#include <cuda_fp16.h>
#include <math.h>
#include <stdint.h>

#define Bq 4
#define Sq 2048
#define HIDq 1024
#define NHq 4
#define Dq 256
#define IMq 2048
#define Eq 4
#define Tq (Bq*Sq)

typedef __half h16;

// ---------------- scratch ----------------
__device__ h16 g_Xhi[Tq*HIDq], g_Xlo[Tq*HIDq];
__device__ h16 g_QKhi[2*Tq*HIDq], g_QKlo[2*Tq*HIDq];
__device__ float g_Vf[Tq*HIDq];
__device__ h16 g_Vthi[HIDq*Tq];
__device__ float g_S[67108864];
__device__ h16 g_Phi[67108864];
__device__ h16 g_Ohi[Tq*HIDq];
__device__ float g_H1[Tq*HIDq], g_Xp[Tq*HIDq];
__device__ h16 g_X2hi[Tq*HIDq];
__device__ h16 g_G4[(long long)Tq*IMq*Eq];
__device__ h16 g_GU4[(long long)Tq*IMq*Eq];
__device__ float g_RW[Tq*Eq];
__device__ h16 g_WqkThi[2*HIDq*HIDq], g_WqkTlo[2*HIDq*HIDq];
__device__ h16 g_WvThi[HIDq*HIDq];
__device__ h16 g_WoThi[HIDq*HIDq];
__device__ h16 g_GThi[Eq*IMq*HIDq];
__device__ h16 g_UThi[Eq*IMq*HIDq];
__device__ h16 g_DThi[(long long)Eq*HIDq*IMq];

// ---------------- helpers ----------------
__device__ __forceinline__ uint32_t smem_u32(const void* p) {
    uint32_t a;
    asm("{ .reg .u64 t; cvta.to.shared.u64 t, %1; cvt.u32.u64 %0, t; }" : "=r"(a) : "l"(p));
    return a;
}
__device__ __forceinline__ void hsplit(float v, h16& h, h16& l) {
    h = __float2half(v);
    l = __float2half(v - __half2float(h));
}
#define MMAH(c, a0,a1,a2,a3, b0,b1) \
    asm volatile("mma.sync.aligned.m16n8k16.row.col.f32.f16.f16.f32 " \
        "{%0,%1,%2,%3}, {%4,%5,%6,%7}, {%8,%9}, {%0,%1,%2,%3};" \
        : "+f"((c)[0]), "+f"((c)[1]), "+f"((c)[2]), "+f"((c)[3]) \
        : "r"(a0), "r"(a1), "r"(a2), "r"(a3), "r"(b0), "r"(b1))
#define LDSM4(r0,r1,r2,r3, addr) \
    asm volatile("ldmatrix.sync.aligned.m8n8.x4.shared.b16 {%0,%1,%2,%3}, [%4];" \
        : "=r"(r0), "=r"(r1), "=r"(r2), "=r"(r3) : "r"(addr))
#define CPA16(s, g) asm volatile("cp.async.cg.shared.global [%0], [%1], 16;" :: "r"(s), "l"(g))
#define CPA_COMMIT() asm volatile("cp.async.commit_group;")

// EPI codes.  SPLIT: 0 = fp32 C, 1 = h16 hi only, 2 = h16 hi+lo.
enum { EPI_NONE = 0, EPI_ELU1, EPI_SILU, EPI_ADD, EPI_MULSCALE };
#define TILE_B 10240
#define SMEM_DYN1 61440          // 1-term: 3 stages * 2 tiles
#define SMEM_DYN3 81920          // 3-term: 2 stages * 4 tiles

// ---------------- 1-term wide-warp GEMM: 128x128 tile, 4 warps of 64x64, 3 stages, 3 CTAs/SM ----------------
template<int EPI, int SPLIT>
__global__ __launch_bounds__(128, 3)
void wgemm(int K,
           const h16* __restrict__ A, int lda, long long sAb, long long sAh,
           const h16* __restrict__ B, int ldb, long long sBb, long long sBh,
           float* C, h16* Chi,
           int ldc, long long sCb, long long sCh,
           const void* __restrict__ Dp,
           const float* __restrict__ scale, int sstride) {
    constexpr int STAGES = 3;
    constexpr int STAGE_BYTES = 2 * TILE_B;

    extern __shared__ char smc[];
    const int t = threadIdx.x;
    const int lane = t & 31, wid = t >> 5;
    const int wm = wid & 1, wn = wid >> 1;      // 2x2 warps, each 64(M) x 64(N)
    const int zb = blockIdx.z >> 2, zh = blockIdx.z & 3;
    const int row0 = blockIdx.y * 128, col0 = blockIdx.x * 128;

    A += (long long)zb * sAb + (long long)zh * sAh;
    B += (long long)zb * sBb + (long long)zh * sBh;
    const long long coff = (long long)zb * sCb + (long long)zh * sCh;

    float c[4][8][4];
    #pragma unroll
    for (int i = 0; i < 4; i++)
        #pragma unroll
        for (int j = 0; j < 8; j++)
            #pragma unroll
            for (int k = 0; k < 4; k++) c[i][j][k] = 0.f;

    const int nkt = K >> 5;
    const uint32_t smu = smem_u32(smc);

    auto stage = [&](int kt, int buf) {
        const int k0 = kt << 5;
        const uint32_t sb = smu + buf * STAGE_BYTES;
        #pragma unroll
        for (int i = 0; i < 8; i++) {
            int chunk = t + (i << 7);
            int tile = chunk >> 9;
            int idx = chunk & 511;
            int row = idx >> 2;
            int q = idx & 3;
            const h16* g;
            if (tile == 0) g = A + (long long)(row0 + row) * lda + k0 + q * 8;
            else           g = B + (long long)(col0 + row) * ldb + k0 + q * 8;
            CPA16(sb + tile * TILE_B + row * 80 + q * 16, g);
        }
        CPA_COMMIT();
    };

    stage(0, 0);
    if (1 < nkt) stage(1, 1);

    for (int kt = 0; kt < nkt; kt++) {
        if (kt + STAGES - 1 < nkt)
            stage(kt + STAGES - 1, (kt + STAGES - 1) % STAGES);
        int rem = nkt - 1 - kt;
        if (rem > STAGES - 1) rem = STAGES - 1;
        if (rem >= 2)      asm volatile("cp.async.wait_group 2;");
        else if (rem == 1) asm volatile("cp.async.wait_group 1;");
        else               asm volatile("cp.async.wait_group 0;");
        __syncthreads();
        const uint32_t sA = smu + (kt % STAGES) * STAGE_BYTES;
        const uint32_t sB = sA + TILE_B;

        #pragma unroll
        for (int k16 = 0; k16 < 2; k16++) {
            const int kc = k16 << 4;
            uint32_t bh[8][2];
            const uint32_t brow = (uint32_t)(wn * 64 + (lane & 7) + ((lane & 16) ? 8 : 0));
            const uint32_t boff = brow * 80 + (uint32_t)(kc + ((lane & 8) ? 8 : 0)) * 2;
            #pragma unroll
            for (int np = 0; np < 4; np++)
                LDSM4(bh[2*np][0], bh[2*np][1], bh[2*np+1][0], bh[2*np+1][1],
                      sB + boff + np * 16 * 80);
            const uint32_t aoff = (uint32_t)(wm * 64 + (lane & 15)) * 80
                                + (uint32_t)(kc + ((lane >> 4) << 3)) * 2;
            #pragma unroll
            for (int mt = 0; mt < 4; mt++) {
                uint32_t a0, a1, a2, a3;
                LDSM4(a0, a1, a2, a3, sA + aoff + mt * 16 * 80);
                #pragma unroll
                for (int nt = 0; nt < 8; nt++)
                    MMAH(c[mt][nt], a0, a1, a2, a3, bh[nt][0], bh[nt][1]);
            }
        }
        __syncthreads();
    }

    #pragma unroll
    for (int mt = 0; mt < 4; mt++) {
        #pragma unroll
        for (int half = 0; half < 2; half++) {
            const long long r = row0 + wm * 64 + mt * 16 + (lane >> 2) + half * 8;
            float sc = 0.f;
            if (EPI == EPI_MULSCALE) sc = __ldg(scale + r * sstride + zh);
            #pragma unroll
            for (int nt = 0; nt < 8; nt++) {
                const long long gi = r * ldc + col0 + wn * 64 + nt * 8 + (lane & 3) * 2;
                float v0 = c[mt][nt][half * 2 + 0];
                float v1 = c[mt][nt][half * 2 + 1];
                if (EPI == EPI_SILU) {
                    v0 = v0 / (1.f + expf(-v0));
                    v1 = v1 / (1.f + expf(-v1));
                } else if (EPI == EPI_ADD) {
                    float2 d = *(const float2*)((const float*)Dp + coff + gi);
                    v0 += d.x; v1 += d.y;
                } else if (EPI == EPI_MULSCALE) {
                    __half2 d = *(const __half2*)((const h16*)Dp + coff + gi);
                    v0 *= __half2float(d.x) * sc;
                    v1 *= __half2float(d.y) * sc;
                }
                if (SPLIT == 1) {
                    __half2 hp; hp.x = __float2half(v0); hp.y = __float2half(v1);
                    *(__half2*)(Chi + coff + gi) = hp;
                } else {
                    *(float2*)(C + coff + gi) = make_float2(v0, v1);
                }
            }
        }
    }
}

// ---------------- 3-term wide-warp GEMM: 128x128 tile, 4 warps of 64x64, 2 stages ----------------
// D += Ah*Bh + Ah*Bl + Al*Bh
template<int EPI, int SPLIT>
__global__ __launch_bounds__(128, 2)
void wgemm3(int K,
            const h16* __restrict__ Ahi, const h16* __restrict__ Alo,
            int lda, long long sAb, long long sAh,
            const h16* __restrict__ Bhi, const h16* __restrict__ Blo,
            int ldb, long long sBb, long long sBh,
            float* C, h16* Chi, h16* Clo,
            int ldc, long long sCb, long long sCh) {
    constexpr int STAGE_BYTES = 4 * TILE_B;

    extern __shared__ char smc[];
    const int t = threadIdx.x;
    const int lane = t & 31, wid = t >> 5;
    const int wm = wid & 1, wn = wid >> 1;
    const int zb = blockIdx.z >> 2, zh = blockIdx.z & 3;
    const int row0 = blockIdx.y * 128, col0 = blockIdx.x * 128;

    Ahi += (long long)zb * sAb + (long long)zh * sAh;
    Alo += (long long)zb * sAb + (long long)zh * sAh;
    Bhi += (long long)zb * sBb + (long long)zh * sBh;
    Blo += (long long)zb * sBb + (long long)zh * sBh;
    const long long coff = (long long)zb * sCb + (long long)zh * sCh;

    float c[4][8][4];
    #pragma unroll
    for (int i = 0; i < 4; i++)
        #pragma unroll
        for (int j = 0; j < 8; j++)
            #pragma unroll
            for (int k = 0; k < 4; k++) c[i][j][k] = 0.f;

    const int nkt = K >> 5;
    const uint32_t smu = smem_u32(smc);

    // tiles: 0=Ah, 1=Bh, 2=Al, 3=Bl
    auto stage = [&](int kt, int buf) {
        const int k0 = kt << 5;
        const uint32_t sb = smu + buf * STAGE_BYTES;
        #pragma unroll
        for (int i = 0; i < 16; i++) {
            int chunk = t + (i << 7);
            int tile = chunk >> 9;
            int idx = chunk & 511;
            int row = idx >> 2;
            int q = idx & 3;
            const h16* g;
            if (tile == 0)      g = Ahi + (long long)(row0 + row) * lda + k0 + q * 8;
            else if (tile == 1) g = Bhi + (long long)(col0 + row) * ldb + k0 + q * 8;
            else if (tile == 2) g = Alo + (long long)(row0 + row) * lda + k0 + q * 8;
            else                g = Blo + (long long)(col0 + row) * ldb + k0 + q * 8;
            CPA16(sb + tile * TILE_B + row * 80 + q * 16, g);
        }
        CPA_COMMIT();
    };

    stage(0, 0);
    for (int kt = 0; kt < nkt; kt++) {
        if (kt + 1 < nkt) {
            stage(kt + 1, (kt + 1) & 1);
            asm volatile("cp.async.wait_group 1;");
        } else {
            asm volatile("cp.async.wait_group 0;");
        }
        __syncthreads();
        const uint32_t sb  = smu + (kt & 1) * STAGE_BYTES;
        const uint32_t sAh = sb;
        const uint32_t sBh = sb + TILE_B;
        const uint32_t sAl = sb + 2 * TILE_B;
        const uint32_t sBl = sb + 3 * TILE_B;

        #pragma unroll
        for (int k16 = 0; k16 < 2; k16++) {
            const int kc = k16 << 4;
            uint32_t bh[8][2], bl[8][2];
            const uint32_t brow = (uint32_t)(wn * 64 + (lane & 7) + ((lane & 16) ? 8 : 0));
            const uint32_t boff = brow * 80 + (uint32_t)(kc + ((lane & 8) ? 8 : 0)) * 2;
            #pragma unroll
            for (int np = 0; np < 4; np++) {
                LDSM4(bh[2*np][0], bh[2*np][1], bh[2*np+1][0], bh[2*np+1][1],
                      sBh + boff + np * 16 * 80);
                LDSM4(bl[2*np][0], bl[2*np][1], bl[2*np+1][0], bl[2*np+1][1],
                      sBl + boff + np * 16 * 80);
            }
            const uint32_t aoff = (uint32_t)(wm * 64 + (lane & 15)) * 80
                                + (uint32_t)(kc + ((lane >> 4) << 3)) * 2;
            #pragma unroll
            for (int mt = 0; mt < 4; mt++) {
                uint32_t ah0, ah1, ah2, ah3, al0, al1, al2, al3;
                LDSM4(ah0, ah1, ah2, ah3, sAh + aoff + mt * 16 * 80);
                LDSM4(al0, al1, al2, al3, sAl + aoff + mt * 16 * 80);
                #pragma unroll
                for (int nt = 0; nt < 8; nt++) {
                    MMAH(c[mt][nt], ah0, ah1, ah2, ah3, bh[nt][0], bh[nt][1]);
                    MMAH(c[mt][nt], ah0, ah1, ah2, ah3, bl[nt][0], bl[nt][1]);
                    MMAH(c[mt][nt], al0, al1, al2, al3, bh[nt][0], bh[nt][1]);
                }
            }
        }
        __syncthreads();
    }

    #pragma unroll
    for (int mt = 0; mt < 4; mt++) {
        #pragma unroll
        for (int half = 0; half < 2; half++) {
            const long long r = row0 + wm * 64 + mt * 16 + (lane >> 2) + half * 8;
            #pragma unroll
            for (int nt = 0; nt < 8; nt++) {
                const long long gi = r * ldc + col0 + wn * 64 + nt * 8 + (lane & 3) * 2;
                float v0 = c[mt][nt][half * 2 + 0];
                float v1 = c[mt][nt][half * 2 + 1];
                if (EPI == EPI_ELU1) {
                    v0 = (v0 >= 0.f) ? v0 + 1.f : expf(v0);
                    v1 = (v1 >= 0.f) ? v1 + 1.f : expf(v1);
                }
                if (SPLIT == 2) {
                    h16 h0, l0, h1, l1;
                    hsplit(v0, h0, l0); hsplit(v1, h1, l1);
                    __half2 hp; hp.x = h0; hp.y = h1;
                    __half2 lp; lp.x = l0; lp.y = l1;
                    *(__half2*)(Chi + coff + gi) = hp;
                    *(__half2*)(Clo + coff + gi) = lp;
                } else {
                    *(float2*)(C + coff + gi) = make_float2(v0, v1);
                }
            }
        }
    }
}

// ---------------- reductions ----------------
__device__ __forceinline__ float blk_sum(float v, float* sh) {
    __syncthreads();
    int t = threadIdx.x, lane = t & 31, w = t >> 5;
    #pragma unroll
    for (int o = 16; o; o >>= 1) v += __shfl_down_sync(0xffffffffu, v, o);
    if (lane == 0) sh[w] = v;
    __syncthreads();
    float r = (t < (int)(blockDim.x >> 5)) ? sh[t] : 0.f;
    if (w == 0) {
        #pragma unroll
        for (int o = 16; o; o >>= 1) r += __shfl_down_sync(0xffffffffu, r, o);
        if (t == 0) sh[0] = r;
    }
    __syncthreads();
    return sh[0];
}
__device__ __forceinline__ float blk_max(float v, float* sh) {
    __syncthreads();
    int t = threadIdx.x, lane = t & 31, w = t >> 5;
    #pragma unroll
    for (int o = 16; o; o >>= 1) v = fmaxf(v, __shfl_down_sync(0xffffffffu, v, o));
    if (lane == 0) sh[w] = v;
    __syncthreads();
    float r = (t < (int)(blockDim.x >> 5)) ? sh[t] : -1e30f;
    if (w == 0) {
        #pragma unroll
        for (int o = 16; o; o >>= 1) r = fmaxf(r, __shfl_down_sync(0xffffffffu, r, o));
        if (t == 0) sh[0] = r;
    }
    __syncthreads();
    return sh[0];
}

// ---------------- RMSNorm + fp16 split (lo optional) ----------------
__global__ void rms_k(const float* __restrict__ x, const float* __restrict__ w,
                      float* __restrict__ y, h16* __restrict__ yhi, h16* __restrict__ ylo) {
    __shared__ float sh[32];
    long long row = blockIdx.x;
    const float4 xv = *(const float4*)(x + row * HIDq + threadIdx.x * 4);
    float ss = xv.x*xv.x + xv.y*xv.y + xv.z*xv.z + xv.w*xv.w;
    ss = blk_sum(ss, sh);
    float inv = rsqrtf(ss * (1.0f / HIDq) + 1e-6f);
    const float4 wv = *(const float4*)(w + threadIdx.x * 4);
    float v[4] = { xv.x*inv*wv.x, xv.y*inv*wv.y, xv.z*inv*wv.z, xv.w*inv*wv.w };
    float4 p;
    h16 hb[4], lb[4];
    #pragma unroll
    for (int i = 0; i < 4; i++) {
        ((float*)&p)[i] = v[i];
        hsplit(v[i], hb[i], lb[i]);
    }
    *(float4*)(y + row * HIDq + threadIdx.x * 4) = p;
    *(uint2*)(yhi + row * HIDq + threadIdx.x * 4) = *(uint2*)hb;
    if (ylo)
        *(uint2*)(ylo + row * HIDq + threadIdx.x * 4) = *(uint2*)lb;
}

// ---------------- softmax (hi only) ----------------
__global__ void softmax_k(const float* __restrict__ s, h16* __restrict__ phi) {
    __shared__ float sh[32];
    long long base = (long long)blockIdx.x * Sq;
    int t = threadIdx.x;
    float v[8]; float mx = -1e30f;
    #pragma unroll
    for (int i = 0; i < 8; i++) { v[i] = s[base + t + 256*i]; mx = fmaxf(mx, v[i]); }
    mx = blk_max(mx, sh);
    float sum = 0.f;
    #pragma unroll
    for (int i = 0; i < 8; i++) { v[i] = expf(v[i] - mx); sum += v[i]; }
    sum = blk_sum(sum, sh);
    float inv = 1.0f / sum;
    #pragma unroll
    for (int i = 0; i < 8; i++)
        phi[base + t + 256*i] = __float2half(v[i] * inv);
}

// ---------------- transpose + fp16 split (lo optional) ----------------
__global__ void tsplit_k(const float* __restrict__ in, h16* __restrict__ ohi,
                         h16* __restrict__ olo, int ldin, int ldout,
                         long long sIb, long long sIh, long long sOb, long long sOh) {
    __shared__ float tile[32][33];
    int z = blockIdx.z, zb = z >> 2, zh = z & 3;
    in  += (long long)zb * sIb + (long long)zh * sIh;
    ohi += (long long)zb * sOb + (long long)zh * sOh;
    if (olo) olo += (long long)zb * sOb + (long long)zh * sOh;
    int r0 = blockIdx.y * 32, c0 = blockIdx.x * 32;
    int tx = threadIdx.x, ty = threadIdx.y;
    #pragma unroll
    for (int k = 0; k < 4; k++)
        tile[ty + 8*k][tx] = in[(long long)(r0 + ty + 8*k) * ldin + c0 + tx];
    __syncthreads();
    #pragma unroll
    for (int k = 0; k < 4; k++) {
        float v = tile[tx][ty + 8*k];
        long long oi = (long long)(c0 + ty + 8*k) * ldout + r0 + tx;
        h16 h, l;
        hsplit(v, h, l);
        ohi[oi] = h;
        if (olo) olo[oi] = l;
    }
}

// ---------------- router ----------------
__global__ void router_k(const float* __restrict__ x2, const float* __restrict__ rwt,
                         const float* __restrict__ rb, float* __restrict__ rw) {
    int warp = threadIdx.x >> 5, lane = threadIdx.x & 31;
    long long token = (long long)blockIdx.x * (blockDim.x >> 5) + warp;
    const float* xr = x2 + token * HIDq;
    float a0=0.f, a1=0.f, a2=0.f, a3=0.f;
    for (int k = lane; k < HIDq; k += 32) {
        float xv = xr[k];
        float4 w4 = *(const float4*)(rwt + (long long)k * Eq);
        a0 = fmaf(xv, w4.x, a0); a1 = fmaf(xv, w4.y, a1);
        a2 = fmaf(xv, w4.z, a2); a3 = fmaf(xv, w4.w, a3);
    }
    #pragma unroll
    for (int o = 16; o; o >>= 1) {
        a0 += __shfl_down_sync(0xffffffffu, a0, o);
        a1 += __shfl_down_sync(0xffffffffu, a1, o);
        a2 += __shfl_down_sync(0xffffffffu, a2, o);
        a3 += __shfl_down_sync(0xffffffffu, a3, o);
    }
    if (lane == 0) {
        float l0=a0+rb[0], l1=a1+rb[1], l2=a2+rb[2], l3=a3+rb[3];
        float m = fmaxf(fmaxf(l0,l1), fmaxf(l2,l3));
        float e0=expf(l0-m), e1=expf(l1-m), e2=expf(l2-m), e3=expf(l3-m);
        float inv = 1.0f / (e0+e1+e2+e3);
        float4 o4; o4.x=e0*inv; o4.y=e1*inv; o4.z=e2*inv; o4.w=e3*inv;
        *(float4*)(rw + token * Eq) = o4;
    }
}

// ---------------- balance loss ----------------
__global__ void balance_k(const float* __restrict__ rw, float* __restrict__ out,
                          long long tail_begin, long long out_size) {
    __shared__ float red[1024];
    int t = threadIdx.x;
    float s = 0.f;
    for (int idx = t; idx < Sq * Eq; idx += 1024) {
        int srow = idx / Eq, e = idx % Eq;
        float m = 0.f;
        #pragma unroll
        for (int b = 0; b < Bq; b++) m += rw[((long long)b * Sq + srow) * Eq + e];
        m *= (1.0f / Bq);
        float d = m - 1.0f / Eq;
        s += d * d;
    }
    red[t] = s;
    __syncthreads();
    for (int o = 512; o; o >>= 1) { if (t < o) red[t] += red[t + o]; __syncthreads(); }
    if (t == 0) {
        float loss = red[0] / ((float)Sq * Eq) * 0.01f;
        for (long long i = tail_begin; i < out_size; i++) out[i] = loss;
    }
}

// ---------------- host ----------------
#define SYMF(p, s) float* p; cudaGetSymbolAddress((void**)&p, s)
#define SYMH(p, s) h16* p; cudaGetSymbolAddress((void**)&p, s)

extern "C" void kernel_launch(void* const* d_in, const int* in_sizes, int n_in,
                              void* d_out, int out_size) {
    const float* hidden = (const float*)d_in[0];
    const float* ln1 = (const float*)d_in[1];
    const float* wq = (const float*)d_in[2];
    const float* wk = (const float*)d_in[3];
    const float* wv = (const float*)d_in[4];
    const float* wo = (const float*)d_in[5];
    const float* ln2 = (const float*)d_in[6];
    const float* rwt = (const float*)d_in[7];
    const float* rb = (const float*)d_in[8];
    const float* gw = (const float*)d_in[9];
    const float* uw = (const float*)d_in[10];
    const float* dwn = (const float*)d_in[11];
    float* out = (float*)d_out;

    SYMH(pXhi, g_Xhi); SYMH(pXlo, g_Xlo);
    SYMH(pQKhi, g_QKhi); SYMH(pQKlo, g_QKlo);
    SYMF(pVf, g_Vf);
    SYMH(pVthi, g_Vthi);
    SYMF(pS, g_S); SYMH(pPhi, g_Phi);
    SYMH(pOhi, g_Ohi); SYMF(pH1, g_H1); SYMF(pXp, g_Xp);
    SYMH(pX2hi, g_X2hi);
    SYMH(pG4, g_G4); SYMH(pGU4, g_GU4); SYMF(pRW, g_RW);
    SYMH(pWqkThi, g_WqkThi); SYMH(pWqkTlo, g_WqkTlo);
    SYMH(pWvThi, g_WvThi);
    SYMH(pWoThi, g_WoThi);
    SYMH(pGThi, g_GThi);
    SYMH(pUThi, g_UThi);
    SYMH(pDThi, g_DThi);

    cudaFuncSetAttribute(wgemm3<EPI_ELU1,2>,    cudaFuncAttributeMaxDynamicSharedMemorySize, SMEM_DYN3);
    cudaFuncSetAttribute(wgemm3<EPI_NONE,0>,    cudaFuncAttributeMaxDynamicSharedMemorySize, SMEM_DYN3);
    cudaFuncSetAttribute(wgemm<EPI_NONE,0>,     cudaFuncAttributeMaxDynamicSharedMemorySize, SMEM_DYN1);
    cudaFuncSetAttribute(wgemm<EPI_NONE,1>,     cudaFuncAttributeMaxDynamicSharedMemorySize, SMEM_DYN1);
    cudaFuncSetAttribute(wgemm<EPI_ADD,0>,      cudaFuncAttributeMaxDynamicSharedMemorySize, SMEM_DYN1);
    cudaFuncSetAttribute(wgemm<EPI_SILU,1>,     cudaFuncAttributeMaxDynamicSharedMemorySize, SMEM_DYN1);
    cudaFuncSetAttribute(wgemm<EPI_MULSCALE,1>, cudaFuncAttributeMaxDynamicSharedMemorySize, SMEM_DYN1);

    const long long Z = 0;
    const dim3 tb(32, 8);
    const long long TH = (long long)Tq * HIDq;
    const long long HH = (long long)HIDq * HIDq;

    // 1) rms1 + split (hi+lo: feeds 3-term QK proj)
    rms_k<<<Tq, 256>>>(hidden, ln1, pXp, pXhi, pXlo);

    // 2) weight transposes + split (lo only where 3-term needs it)
    tsplit_k<<<dim3(32,32,1), tb>>>(wq, pWqkThi,      pWqkTlo,      HIDq, HIDq, Z,Z,Z,Z);
    tsplit_k<<<dim3(32,32,1), tb>>>(wk, pWqkThi + HH, pWqkTlo + HH, HIDq, HIDq, Z,Z,Z,Z);
    tsplit_k<<<dim3(32,32,1), tb>>>(wv, pWvThi, nullptr, HIDq, HIDq, Z,Z,Z,Z);
    tsplit_k<<<dim3(32,32,1), tb>>>(wo, pWoThi, nullptr, HIDq, HIDq, Z,Z,Z,Z);
    tsplit_k<<<dim3(64,32,4), tb>>>(gw, pGThi, nullptr, IMq, HIDq, Z,(long long)HIDq*IMq, Z,(long long)IMq*HIDq);
    tsplit_k<<<dim3(64,32,4), tb>>>(uw, pUThi, nullptr, IMq, HIDq, Z,(long long)HIDq*IMq, Z,(long long)IMq*HIDq);
    tsplit_k<<<dim3(32,64,4), tb>>>(dwn, pDThi, nullptr, HIDq, 4*IMq, Z,(long long)IMq*HIDq, Z,(long long)IMq);

    // 3) Q,K projections merged (3-term, z=2), elu+1 + split
    wgemm3<EPI_ELU1,2><<<dim3(8,64,2), 128, SMEM_DYN3>>>(HIDq,
        pXhi, pXlo, HIDq, Z,Z,
        pWqkThi, pWqkTlo, HIDq, Z, HH,
        nullptr, pQKhi, pQKlo, HIDq, Z, TH);

    // 4) V projection (1-term, fp32 out)
    wgemm<EPI_NONE,0><<<dim3(8,64,1), 128, SMEM_DYN1>>>(HIDq,
        pXhi, HIDq, Z,Z, pWvThi, HIDq, Z,Z,
        pVf, nullptr, HIDq, Z,Z, nullptr, nullptr, 0);

    // 5) V transpose per (b,h) (hi only)
    tsplit_k<<<dim3(8,64,16), tb>>>(pVf, pVthi, nullptr, HIDq, Sq,
        (long long)Sq*HIDq, (long long)Dq,
        (long long)NHq*Dq*Sq, (long long)Dq*Sq);

    // 6) scores = Q @ K^T per head (3-term)
    wgemm3<EPI_NONE,0><<<dim3(16,16,16), 128, SMEM_DYN3>>>(Dq,
        pQKhi,      pQKlo,      HIDq, (long long)Sq*HIDq, (long long)Dq,
        pQKhi + TH, pQKlo + TH, HIDq, (long long)Sq*HIDq, (long long)Dq,
        pS, nullptr, nullptr, Sq, (long long)NHq*Sq*Sq, (long long)Sq*Sq);

    // 7) softmax (hi only)
    softmax_k<<<Bq*NHq*Sq, 256>>>(pS, pPhi);

    // 8) O = P @ V per head (1-term)
    wgemm<EPI_NONE,1><<<dim3(2,16,16), 128, SMEM_DYN1>>>(Sq,
        pPhi,  Sq, (long long)NHq*Sq*Sq, (long long)Sq*Sq,
        pVthi, Sq, (long long)NHq*Dq*Sq, (long long)Dq*Sq,
        nullptr, pOhi, HIDq, (long long)Sq*HIDq, (long long)Dq,
        nullptr, nullptr, 0);

    // 9) h1 = hidden + O @ wo (1-term)
    wgemm<EPI_ADD,0><<<dim3(8,64,1), 128, SMEM_DYN1>>>(HIDq,
        pOhi, HIDq, Z,Z, pWoThi, HIDq, Z,Z,
        pH1, nullptr, HIDq, Z,Z, hidden, nullptr, 0);

    // 10) rms2 (hi only), router, balance
    rms_k<<<Tq, 256>>>(pH1, ln2, pXp, pX2hi, nullptr);
    router_k<<<Tq/8, 256>>>(pXp, rwt, rb, pRW);
    balance_k<<<1, 1024>>>(pRW, out, (long long)Tq*HIDq, (long long)out_size);

    // 11) MoE gate: batched z=4, silu -> G4
    wgemm<EPI_SILU,1><<<dim3(16,64,4), 128, SMEM_DYN1>>>(HIDq,
        pX2hi, HIDq, Z,Z,
        pGThi, HIDq, Z, (long long)IMq*HIDq,
        nullptr, pG4, 4*IMq, Z, (long long)IMq,
        nullptr, nullptr, 0);

    // 12) MoE up: batched z=4, fused * G4 * rw[:,e] -> GU4
    wgemm<EPI_MULSCALE,1><<<dim3(16,64,4), 128, SMEM_DYN1>>>(HIDq,
        pX2hi, HIDq, Z,Z,
        pUThi, HIDq, Z, (long long)IMq*HIDq,
        nullptr, pGU4, 4*IMq, Z, (long long)IMq,
        pG4, pRW, Eq);

    // 13) MoE down: out = h1 + GU4 @ DT^T (K=8192)
    wgemm<EPI_ADD,0><<<dim3(8,64,1), 128, SMEM_DYN1>>>(4*IMq,
        pGU4,  4*IMq, Z,Z,
        pDThi, 4*IMq, Z,Z,
        out, nullptr, HIDq, Z,Z, pH1, nullptr, 0);
}

// round 14
// speedup vs baseline: 1.0608x; 1.0608x over previous
#include <cuda_runtime.h>
#include <cuda_fp16.h>
#include <math.h>
#include <stdint.h>

#define Bq 4
#define Sq 2048
#define HIDq 1024
#define NHq 4
#define Dq 256
#define IMq 2048
#define Eq 4
#define Tq (Bq*Sq)

typedef __half h16;

// ---------------- scratch ----------------
__device__ h16 g_Xhi[Tq*HIDq], g_Xlo[Tq*HIDq];
__device__ h16 g_QKhi[2*Tq*HIDq], g_QKlo[2*Tq*HIDq];
__device__ float g_Vf[Tq*HIDq];
__device__ h16 g_Vthi[HIDq*Tq];
__device__ float g_S[67108864];
__device__ h16 g_Phi[67108864];
__device__ h16 g_Ohi[Tq*HIDq];
__device__ float g_H1[Tq*HIDq], g_Xp[Tq*HIDq];
__device__ h16 g_X2hi[Tq*HIDq];
__device__ h16 g_G4[(long long)Tq*IMq*Eq];
__device__ h16 g_GU4[(long long)Tq*IMq*Eq];
__device__ float g_RW[Tq*Eq];
__device__ h16 g_WqkThi[2*HIDq*HIDq], g_WqkTlo[2*HIDq*HIDq];
__device__ h16 g_WvThi[HIDq*HIDq];
__device__ h16 g_WoThi[HIDq*HIDq];
__device__ h16 g_GThi[Eq*IMq*HIDq];
__device__ h16 g_UThi[Eq*IMq*HIDq];
__device__ h16 g_DThi[(long long)Eq*HIDq*IMq];

// ---------------- helpers ----------------
__device__ __forceinline__ uint32_t smem_u32(const void* p) {
    uint32_t a;
    asm("{ .reg .u64 t; cvta.to.shared.u64 t, %1; cvt.u32.u64 %0, t; }" : "=r"(a) : "l"(p));
    return a;
}
__device__ __forceinline__ void hsplit(float v, h16& h, h16& l) {
    h = __float2half(v);
    l = __float2half(v - __half2float(h));
}
#define MMAH(c, a0,a1,a2,a3, b0,b1) \
    asm volatile("mma.sync.aligned.m16n8k16.row.col.f32.f16.f16.f32 " \
        "{%0,%1,%2,%3}, {%4,%5,%6,%7}, {%8,%9}, {%0,%1,%2,%3};" \
        : "+f"((c)[0]), "+f"((c)[1]), "+f"((c)[2]), "+f"((c)[3]) \
        : "r"(a0), "r"(a1), "r"(a2), "r"(a3), "r"(b0), "r"(b1))
#define LDSM4(r0,r1,r2,r3, addr) \
    asm volatile("ldmatrix.sync.aligned.m8n8.x4.shared.b16 {%0,%1,%2,%3}, [%4];" \
        : "=r"(r0), "=r"(r1), "=r"(r2), "=r"(r3) : "r"(addr))
#define CPA16(s, g) asm volatile("cp.async.cg.shared.global [%0], [%1], 16;" :: "r"(s), "l"(g))
#define CPA_COMMIT() asm volatile("cp.async.commit_group;")

// EPI codes.  SPLIT: 0 = fp32 C, 1 = h16 hi only, 2 = h16 hi+lo.
enum { EPI_NONE = 0, EPI_ELU1, EPI_SILU, EPI_ADD, EPI_MULSCALE };
#define TILE_B 10240
#define SMEM_DYN 81920

// ---------------- 1-term wide-warp GEMM: 128x128 tile, 4 warps of 64x64, 4 stages, 2 CTAs/SM ----------------
template<int EPI, int SPLIT>
__global__ __launch_bounds__(128, 2)
void wgemm(int K,
           const h16* __restrict__ A, int lda, long long sAb, long long sAh,
           const h16* __restrict__ B, int ldb, long long sBb, long long sBh,
           float* C, h16* Chi,
           int ldc, long long sCb, long long sCh,
           const void* __restrict__ Dp,
           const float* __restrict__ scale, int sstride) {
    constexpr int STAGES = 4;
    constexpr int STAGE_BYTES = 2 * TILE_B;

    extern __shared__ char smc[];
    const int t = threadIdx.x;
    const int lane = t & 31, wid = t >> 5;
    const int wm = wid & 1, wn = wid >> 1;      // 2x2 warps, each 64(M) x 64(N)
    const int zb = blockIdx.z >> 2, zh = blockIdx.z & 3;
    const int row0 = blockIdx.y * 128, col0 = blockIdx.x * 128;

    A += (long long)zb * sAb + (long long)zh * sAh;
    B += (long long)zb * sBb + (long long)zh * sBh;
    const long long coff = (long long)zb * sCb + (long long)zh * sCh;

    float c[4][8][4];
    #pragma unroll
    for (int i = 0; i < 4; i++)
        #pragma unroll
        for (int j = 0; j < 8; j++)
            #pragma unroll
            for (int k = 0; k < 4; k++) c[i][j][k] = 0.f;

    const int nkt = K >> 5;
    const uint32_t smu = smem_u32(smc);

    auto stage = [&](int kt, int buf) {
        const int k0 = kt << 5;
        const uint32_t sb = smu + buf * STAGE_BYTES;
        #pragma unroll
        for (int i = 0; i < 8; i++) {
            int chunk = t + (i << 7);
            int tile = chunk >> 9;
            int idx = chunk & 511;
            int row = idx >> 2;
            int q = idx & 3;
            const h16* g;
            if (tile == 0) g = A + (long long)(row0 + row) * lda + k0 + q * 8;
            else           g = B + (long long)(col0 + row) * ldb + k0 + q * 8;
            CPA16(sb + tile * TILE_B + row * 80 + q * 16, g);
        }
        CPA_COMMIT();
    };

    stage(0, 0);
    #pragma unroll
    for (int s = 1; s < STAGES - 1; s++)
        if (s < nkt) stage(s, s);

    for (int kt = 0; kt < nkt; kt++) {
        if (kt + STAGES - 1 < nkt)
            stage(kt + STAGES - 1, (kt + STAGES - 1) % STAGES);
        int rem = nkt - 1 - kt;
        if (rem > STAGES - 1) rem = STAGES - 1;
        if (rem >= 3)      asm volatile("cp.async.wait_group 3;");
        else if (rem == 2) asm volatile("cp.async.wait_group 2;");
        else if (rem == 1) asm volatile("cp.async.wait_group 1;");
        else               asm volatile("cp.async.wait_group 0;");
        __syncthreads();
        const uint32_t sA = smu + (kt % STAGES) * STAGE_BYTES;
        const uint32_t sB = sA + TILE_B;

        #pragma unroll
        for (int k16 = 0; k16 < 2; k16++) {
            const int kc = k16 << 4;
            uint32_t bh[8][2];
            const uint32_t brow = (uint32_t)(wn * 64 + (lane & 7) + ((lane & 16) ? 8 : 0));
            const uint32_t boff = brow * 80 + (uint32_t)(kc + ((lane & 8) ? 8 : 0)) * 2;
            #pragma unroll
            for (int np = 0; np < 4; np++)
                LDSM4(bh[2*np][0], bh[2*np][1], bh[2*np+1][0], bh[2*np+1][1],
                      sB + boff + np * 16 * 80);
            const uint32_t aoff = (uint32_t)(wm * 64 + (lane & 15)) * 80
                                + (uint32_t)(kc + ((lane >> 4) << 3)) * 2;
            #pragma unroll
            for (int mt = 0; mt < 4; mt++) {
                uint32_t a0, a1, a2, a3;
                LDSM4(a0, a1, a2, a3, sA + aoff + mt * 16 * 80);
                #pragma unroll
                for (int nt = 0; nt < 8; nt++)
                    MMAH(c[mt][nt], a0, a1, a2, a3, bh[nt][0], bh[nt][1]);
            }
        }
        __syncthreads();
    }

    #pragma unroll
    for (int mt = 0; mt < 4; mt++) {
        #pragma unroll
        for (int half = 0; half < 2; half++) {
            const long long r = row0 + wm * 64 + mt * 16 + (lane >> 2) + half * 8;
            float sc = 0.f;
            if (EPI == EPI_MULSCALE) sc = __ldg(scale + r * sstride + zh);
            #pragma unroll
            for (int nt = 0; nt < 8; nt++) {
                const long long gi = r * ldc + col0 + wn * 64 + nt * 8 + (lane & 3) * 2;
                float v0 = c[mt][nt][half * 2 + 0];
                float v1 = c[mt][nt][half * 2 + 1];
                if (EPI == EPI_SILU) {
                    v0 = v0 / (1.f + expf(-v0));
                    v1 = v1 / (1.f + expf(-v1));
                } else if (EPI == EPI_ADD) {
                    float2 d = *(const float2*)((const float*)Dp + coff + gi);
                    v0 += d.x; v1 += d.y;
                } else if (EPI == EPI_MULSCALE) {
                    __half2 d = *(const __half2*)((const h16*)Dp + coff + gi);
                    v0 *= __half2float(d.x) * sc;
                    v1 *= __half2float(d.y) * sc;
                }
                if (SPLIT == 1) {
                    __half2 hp; hp.x = __float2half(v0); hp.y = __float2half(v1);
                    *(__half2*)(Chi + coff + gi) = hp;
                } else {
                    *(float2*)(C + coff + gi) = make_float2(v0, v1);
                }
            }
        }
    }
}

// ---------------- 3-term wide-warp GEMM: 128x128 tile, 4 warps of 64x64, 2 stages ----------------
// D += Ah*Bh + Ah*Bl + Al*Bh
template<int EPI, int SPLIT>
__global__ __launch_bounds__(128, 2)
void wgemm3(int K,
            const h16* __restrict__ Ahi, const h16* __restrict__ Alo,
            int lda, long long sAb, long long sAh,
            const h16* __restrict__ Bhi, const h16* __restrict__ Blo,
            int ldb, long long sBb, long long sBh,
            float* C, h16* Chi, h16* Clo,
            int ldc, long long sCb, long long sCh) {
    constexpr int STAGE_BYTES = 4 * TILE_B;

    extern __shared__ char smc[];
    const int t = threadIdx.x;
    const int lane = t & 31, wid = t >> 5;
    const int wm = wid & 1, wn = wid >> 1;
    const int zb = blockIdx.z >> 2, zh = blockIdx.z & 3;
    const int row0 = blockIdx.y * 128, col0 = blockIdx.x * 128;

    Ahi += (long long)zb * sAb + (long long)zh * sAh;
    Alo += (long long)zb * sAb + (long long)zh * sAh;
    Bhi += (long long)zb * sBb + (long long)zh * sBh;
    Blo += (long long)zb * sBb + (long long)zh * sBh;
    const long long coff = (long long)zb * sCb + (long long)zh * sCh;

    float c[4][8][4];
    #pragma unroll
    for (int i = 0; i < 4; i++)
        #pragma unroll
        for (int j = 0; j < 8; j++)
            #pragma unroll
            for (int k = 0; k < 4; k++) c[i][j][k] = 0.f;

    const int nkt = K >> 5;
    const uint32_t smu = smem_u32(smc);

    // tiles: 0=Ah, 1=Bh, 2=Al, 3=Bl
    auto stage = [&](int kt, int buf) {
        const int k0 = kt << 5;
        const uint32_t sb = smu + buf * STAGE_BYTES;
        #pragma unroll
        for (int i = 0; i < 16; i++) {
            int chunk = t + (i << 7);
            int tile = chunk >> 9;
            int idx = chunk & 511;
            int row = idx >> 2;
            int q = idx & 3;
            const h16* g;
            if (tile == 0)      g = Ahi + (long long)(row0 + row) * lda + k0 + q * 8;
            else if (tile == 1) g = Bhi + (long long)(col0 + row) * ldb + k0 + q * 8;
            else if (tile == 2) g = Alo + (long long)(row0 + row) * lda + k0 + q * 8;
            else                g = Blo + (long long)(col0 + row) * ldb + k0 + q * 8;
            CPA16(sb + tile * TILE_B + row * 80 + q * 16, g);
        }
        CPA_COMMIT();
    };

    stage(0, 0);
    for (int kt = 0; kt < nkt; kt++) {
        if (kt + 1 < nkt) {
            stage(kt + 1, (kt + 1) & 1);
            asm volatile("cp.async.wait_group 1;");
        } else {
            asm volatile("cp.async.wait_group 0;");
        }
        __syncthreads();
        const uint32_t sb  = smu + (kt & 1) * STAGE_BYTES;
        const uint32_t sAh = sb;
        const uint32_t sBh = sb + TILE_B;
        const uint32_t sAl = sb + 2 * TILE_B;
        const uint32_t sBl = sb + 3 * TILE_B;

        #pragma unroll
        for (int k16 = 0; k16 < 2; k16++) {
            const int kc = k16 << 4;
            uint32_t bh[8][2], bl[8][2];
            const uint32_t brow = (uint32_t)(wn * 64 + (lane & 7) + ((lane & 16) ? 8 : 0));
            const uint32_t boff = brow * 80 + (uint32_t)(kc + ((lane & 8) ? 8 : 0)) * 2;
            #pragma unroll
            for (int np = 0; np < 4; np++) {
                LDSM4(bh[2*np][0], bh[2*np][1], bh[2*np+1][0], bh[2*np+1][1],
                      sBh + boff + np * 16 * 80);
                LDSM4(bl[2*np][0], bl[2*np][1], bl[2*np+1][0], bl[2*np+1][1],
                      sBl + boff + np * 16 * 80);
            }
            const uint32_t aoff = (uint32_t)(wm * 64 + (lane & 15)) * 80
                                + (uint32_t)(kc + ((lane >> 4) << 3)) * 2;
            #pragma unroll
            for (int mt = 0; mt < 4; mt++) {
                uint32_t ah0, ah1, ah2, ah3, al0, al1, al2, al3;
                LDSM4(ah0, ah1, ah2, ah3, sAh + aoff + mt * 16 * 80);
                LDSM4(al0, al1, al2, al3, sAl + aoff + mt * 16 * 80);
                #pragma unroll
                for (int nt = 0; nt < 8; nt++) {
                    MMAH(c[mt][nt], ah0, ah1, ah2, ah3, bh[nt][0], bh[nt][1]);
                    MMAH(c[mt][nt], ah0, ah1, ah2, ah3, bl[nt][0], bl[nt][1]);
                    MMAH(c[mt][nt], al0, al1, al2, al3, bh[nt][0], bh[nt][1]);
                }
            }
        }
        __syncthreads();
    }

    #pragma unroll
    for (int mt = 0; mt < 4; mt++) {
        #pragma unroll
        for (int half = 0; half < 2; half++) {
            const long long r = row0 + wm * 64 + mt * 16 + (lane >> 2) + half * 8;
            #pragma unroll
            for (int nt = 0; nt < 8; nt++) {
                const long long gi = r * ldc + col0 + wn * 64 + nt * 8 + (lane & 3) * 2;
                float v0 = c[mt][nt][half * 2 + 0];
                float v1 = c[mt][nt][half * 2 + 1];
                if (EPI == EPI_ELU1) {
                    v0 = (v0 >= 0.f) ? v0 + 1.f : expf(v0);
                    v1 = (v1 >= 0.f) ? v1 + 1.f : expf(v1);
                }
                if (SPLIT == 2) {
                    h16 h0, l0, h1, l1;
                    hsplit(v0, h0, l0); hsplit(v1, h1, l1);
                    __half2 hp; hp.x = h0; hp.y = h1;
                    __half2 lp; lp.x = l0; lp.y = l1;
                    *(__half2*)(Chi + coff + gi) = hp;
                    *(__half2*)(Clo + coff + gi) = lp;
                } else {
                    *(float2*)(C + coff + gi) = make_float2(v0, v1);
                }
            }
        }
    }
}

// ---------------- reductions ----------------
__device__ __forceinline__ float blk_sum(float v, float* sh) {
    __syncthreads();
    int t = threadIdx.x, lane = t & 31, w = t >> 5;
    #pragma unroll
    for (int o = 16; o; o >>= 1) v += __shfl_down_sync(0xffffffffu, v, o);
    if (lane == 0) sh[w] = v;
    __syncthreads();
    float r = (t < (int)(blockDim.x >> 5)) ? sh[t] : 0.f;
    if (w == 0) {
        #pragma unroll
        for (int o = 16; o; o >>= 1) r += __shfl_down_sync(0xffffffffu, r, o);
        if (t == 0) sh[0] = r;
    }
    __syncthreads();
    return sh[0];
}
__device__ __forceinline__ float blk_max(float v, float* sh) {
    __syncthreads();
    int t = threadIdx.x, lane = t & 31, w = t >> 5;
    #pragma unroll
    for (int o = 16; o; o >>= 1) v = fmaxf(v, __shfl_down_sync(0xffffffffu, v, o));
    if (lane == 0) sh[w] = v;
    __syncthreads();
    float r = (t < (int)(blockDim.x >> 5)) ? sh[t] : -1e30f;
    if (w == 0) {
        #pragma unroll
        for (int o = 16; o; o >>= 1) r = fmaxf(r, __shfl_down_sync(0xffffffffu, r, o));
        if (t == 0) sh[0] = r;
    }
    __syncthreads();
    return sh[0];
}

// ---------------- RMSNorm + fp16 split (lo optional) ----------------
__global__ void rms_k(const float* __restrict__ x, const float* __restrict__ w,
                      float* __restrict__ y, h16* __restrict__ yhi, h16* __restrict__ ylo) {
    __shared__ float sh[32];
    long long row = blockIdx.x;
    const float4 xv = *(const float4*)(x + row * HIDq + threadIdx.x * 4);
    float ss = xv.x*xv.x + xv.y*xv.y + xv.z*xv.z + xv.w*xv.w;
    ss = blk_sum(ss, sh);
    float inv = rsqrtf(ss * (1.0f / HIDq) + 1e-6f);
    const float4 wv = *(const float4*)(w + threadIdx.x * 4);
    float v[4] = { xv.x*inv*wv.x, xv.y*inv*wv.y, xv.z*inv*wv.z, xv.w*inv*wv.w };
    float4 p;
    h16 hb[4], lb[4];
    #pragma unroll
    for (int i = 0; i < 4; i++) {
        ((float*)&p)[i] = v[i];
        hsplit(v[i], hb[i], lb[i]);
    }
    *(float4*)(y + row * HIDq + threadIdx.x * 4) = p;
    *(uint2*)(yhi + row * HIDq + threadIdx.x * 4) = *(uint2*)hb;
    if (ylo)
        *(uint2*)(ylo + row * HIDq + threadIdx.x * 4) = *(uint2*)lb;
}

// ---------------- softmax (hi only) ----------------
__global__ void softmax_k(const float* __restrict__ s, h16* __restrict__ phi) {
    __shared__ float sh[32];
    long long base = (long long)blockIdx.x * Sq;
    int t = threadIdx.x;
    float v[8]; float mx = -1e30f;
    #pragma unroll
    for (int i = 0; i < 8; i++) { v[i] = s[base + t + 256*i]; mx = fmaxf(mx, v[i]); }
    mx = blk_max(mx, sh);
    float sum = 0.f;
    #pragma unroll
    for (int i = 0; i < 8; i++) { v[i] = expf(v[i] - mx); sum += v[i]; }
    sum = blk_sum(sum, sh);
    float inv = 1.0f / sum;
    #pragma unroll
    for (int i = 0; i < 8; i++)
        phi[base + t + 256*i] = __float2half(v[i] * inv);
}

// ---------------- transpose + fp16 split (lo optional) ----------------
__global__ void tsplit_k(const float* __restrict__ in, h16* __restrict__ ohi,
                         h16* __restrict__ olo, int ldin, int ldout,
                         long long sIb, long long sIh, long long sOb, long long sOh) {
    __shared__ float tile[32][33];
    int z = blockIdx.z, zb = z >> 2, zh = z & 3;
    in  += (long long)zb * sIb + (long long)zh * sIh;
    ohi += (long long)zb * sOb + (long long)zh * sOh;
    if (olo) olo += (long long)zb * sOb + (long long)zh * sOh;
    int r0 = blockIdx.y * 32, c0 = blockIdx.x * 32;
    int tx = threadIdx.x, ty = threadIdx.y;
    #pragma unroll
    for (int k = 0; k < 4; k++)
        tile[ty + 8*k][tx] = in[(long long)(r0 + ty + 8*k) * ldin + c0 + tx];
    __syncthreads();
    #pragma unroll
    for (int k = 0; k < 4; k++) {
        float v = tile[tx][ty + 8*k];
        long long oi = (long long)(c0 + ty + 8*k) * ldout + r0 + tx;
        h16 h, l;
        hsplit(v, h, l);
        ohi[oi] = h;
        if (olo) olo[oi] = l;
    }
}

// ---------------- router ----------------
__global__ void router_k(const float* __restrict__ x2, const float* __restrict__ rwt,
                         const float* __restrict__ rb, float* __restrict__ rw) {
    int warp = threadIdx.x >> 5, lane = threadIdx.x & 31;
    long long token = (long long)blockIdx.x * (blockDim.x >> 5) + warp;
    const float* xr = x2 + token * HIDq;
    float a0=0.f, a1=0.f, a2=0.f, a3=0.f;
    for (int k = lane; k < HIDq; k += 32) {
        float xv = xr[k];
        float4 w4 = *(const float4*)(rwt + (long long)k * Eq);
        a0 = fmaf(xv, w4.x, a0); a1 = fmaf(xv, w4.y, a1);
        a2 = fmaf(xv, w4.z, a2); a3 = fmaf(xv, w4.w, a3);
    }
    #pragma unroll
    for (int o = 16; o; o >>= 1) {
        a0 += __shfl_down_sync(0xffffffffu, a0, o);
        a1 += __shfl_down_sync(0xffffffffu, a1, o);
        a2 += __shfl_down_sync(0xffffffffu, a2, o);
        a3 += __shfl_down_sync(0xffffffffu, a3, o);
    }
    if (lane == 0) {
        float l0=a0+rb[0], l1=a1+rb[1], l2=a2+rb[2], l3=a3+rb[3];
        float m = fmaxf(fmaxf(l0,l1), fmaxf(l2,l3));
        float e0=expf(l0-m), e1=expf(l1-m), e2=expf(l2-m), e3=expf(l3-m);
        float inv = 1.0f / (e0+e1+e2+e3);
        float4 o4; o4.x=e0*inv; o4.y=e1*inv; o4.z=e2*inv; o4.w=e3*inv;
        *(float4*)(rw + token * Eq) = o4;
    }
}

// ---------------- balance loss ----------------
__global__ void balance_k(const float* __restrict__ rw, float* __restrict__ out,
                          long long tail_begin, long long out_size) {
    __shared__ float red[1024];
    int t = threadIdx.x;
    float s = 0.f;
    for (int idx = t; idx < Sq * Eq; idx += 1024) {
        int srow = idx / Eq, e = idx % Eq;
        float m = 0.f;
        #pragma unroll
        for (int b = 0; b < Bq; b++) m += rw[((long long)b * Sq + srow) * Eq + e];
        m *= (1.0f / Bq);
        float d = m - 1.0f / Eq;
        s += d * d;
    }
    red[t] = s;
    __syncthreads();
    for (int o = 512; o; o >>= 1) { if (t < o) red[t] += red[t + o]; __syncthreads(); }
    if (t == 0) {
        float loss = red[0] / ((float)Sq * Eq) * 0.01f;
        for (long long i = tail_begin; i < out_size; i++) out[i] = loss;
    }
}

// ---------------- host ----------------
#define SYMF(p, s) float* p; cudaGetSymbolAddress((void**)&p, s)
#define SYMH(p, s) h16* p; cudaGetSymbolAddress((void**)&p, s)

extern "C" void kernel_launch(void* const* d_in, const int* in_sizes, int n_in,
                              void* d_out, int out_size) {
    const float* hidden = (const float*)d_in[0];
    const float* ln1 = (const float*)d_in[1];
    const float* wq = (const float*)d_in[2];
    const float* wk = (const float*)d_in[3];
    const float* wv = (const float*)d_in[4];
    const float* wo = (const float*)d_in[5];
    const float* ln2 = (const float*)d_in[6];
    const float* rwt = (const float*)d_in[7];
    const float* rb = (const float*)d_in[8];
    const float* gw = (const float*)d_in[9];
    const float* uw = (const float*)d_in[10];
    const float* dwn = (const float*)d_in[11];
    float* out = (float*)d_out;

    SYMH(pXhi, g_Xhi); SYMH(pXlo, g_Xlo);
    SYMH(pQKhi, g_QKhi); SYMH(pQKlo, g_QKlo);
    SYMF(pVf, g_Vf);
    SYMH(pVthi, g_Vthi);
    SYMF(pS, g_S); SYMH(pPhi, g_Phi);
    SYMH(pOhi, g_Ohi); SYMF(pH1, g_H1); SYMF(pXp, g_Xp);
    SYMH(pX2hi, g_X2hi);
    SYMH(pG4, g_G4); SYMH(pGU4, g_GU4); SYMF(pRW, g_RW);
    SYMH(pWqkThi, g_WqkThi); SYMH(pWqkTlo, g_WqkTlo);
    SYMH(pWvThi, g_WvThi);
    SYMH(pWoThi, g_WoThi);
    SYMH(pGThi, g_GThi);
    SYMH(pUThi, g_UThi);
    SYMH(pDThi, g_DThi);

    cudaFuncSetAttribute(wgemm3<EPI_ELU1,2>,    cudaFuncAttributeMaxDynamicSharedMemorySize, SMEM_DYN);
    cudaFuncSetAttribute(wgemm3<EPI_NONE,0>,    cudaFuncAttributeMaxDynamicSharedMemorySize, SMEM_DYN);
    cudaFuncSetAttribute(wgemm<EPI_NONE,0>,     cudaFuncAttributeMaxDynamicSharedMemorySize, SMEM_DYN);
    cudaFuncSetAttribute(wgemm<EPI_NONE,1>,     cudaFuncAttributeMaxDynamicSharedMemorySize, SMEM_DYN);
    cudaFuncSetAttribute(wgemm<EPI_ADD,0>,      cudaFuncAttributeMaxDynamicSharedMemorySize, SMEM_DYN);
    cudaFuncSetAttribute(wgemm<EPI_SILU,1>,     cudaFuncAttributeMaxDynamicSharedMemorySize, SMEM_DYN);
    cudaFuncSetAttribute(wgemm<EPI_MULSCALE,1>, cudaFuncAttributeMaxDynamicSharedMemorySize, SMEM_DYN);

    const long long Z = 0;
    const dim3 tb(32, 8);
    const long long TH = (long long)Tq * HIDq;
    const long long HH = (long long)HIDq * HIDq;

    // 1) rms1 + split (hi+lo: feeds 3-term QK proj)
    rms_k<<<Tq, 256>>>(hidden, ln1, pXp, pXhi, pXlo);

    // 2) weight transposes + split (lo only where 3-term needs it)
    tsplit_k<<<dim3(32,32,1), tb>>>(wq, pWqkThi,      pWqkTlo,      HIDq, HIDq, Z,Z,Z,Z);
    tsplit_k<<<dim3(32,32,1), tb>>>(wk, pWqkThi + HH, pWqkTlo + HH, HIDq, HIDq, Z,Z,Z,Z);
    tsplit_k<<<dim3(32,32,1), tb>>>(wv, pWvThi, nullptr, HIDq, HIDq, Z,Z,Z,Z);
    tsplit_k<<<dim3(32,32,1), tb>>>(wo, pWoThi, nullptr, HIDq, HIDq, Z,Z,Z,Z);
    tsplit_k<<<dim3(64,32,4), tb>>>(gw, pGThi, nullptr, IMq, HIDq, Z,(long long)HIDq*IMq, Z,(long long)IMq*HIDq);
    tsplit_k<<<dim3(64,32,4), tb>>>(uw, pUThi, nullptr, IMq, HIDq, Z,(long long)HIDq*IMq, Z,(long long)IMq*HIDq);
    tsplit_k<<<dim3(32,64,4), tb>>>(dwn, pDThi, nullptr, HIDq, 4*IMq, Z,(long long)IMq*HIDq, Z,(long long)IMq);

    // 3) Q,K projections merged (3-term, z=2), elu+1 + split
    wgemm3<EPI_ELU1,2><<<dim3(8,64,2), 128, SMEM_DYN>>>(HIDq,
        pXhi, pXlo, HIDq, Z,Z,
        pWqkThi, pWqkTlo, HIDq, Z, HH,
        nullptr, pQKhi, pQKlo, HIDq, Z, TH);

    // 4) V projection (1-term, fp32 out)
    wgemm<EPI_NONE,0><<<dim3(8,64,1), 128, SMEM_DYN>>>(HIDq,
        pXhi, HIDq, Z,Z, pWvThi, HIDq, Z,Z,
        pVf, nullptr, HIDq, Z,Z, nullptr, nullptr, 0);

    // 5) V transpose per (b,h) (hi only)
    tsplit_k<<<dim3(8,64,16), tb>>>(pVf, pVthi, nullptr, HIDq, Sq,
        (long long)Sq*HIDq, (long long)Dq,
        (long long)NHq*Dq*Sq, (long long)Dq*Sq);

    // 6) scores = Q @ K^T per head (3-term)
    wgemm3<EPI_NONE,0><<<dim3(16,16,16), 128, SMEM_DYN>>>(Dq,
        pQKhi,      pQKlo,      HIDq, (long long)Sq*HIDq, (long long)Dq,
        pQKhi + TH, pQKlo + TH, HIDq, (long long)Sq*HIDq, (long long)Dq,
        pS, nullptr, nullptr, Sq, (long long)NHq*Sq*Sq, (long long)Sq*Sq);

    // 7) softmax (hi only)
    softmax_k<<<Bq*NHq*Sq, 256>>>(pS, pPhi);

    // 8) O = P @ V per head (1-term)
    wgemm<EPI_NONE,1><<<dim3(2,16,16), 128, SMEM_DYN>>>(Sq,
        pPhi,  Sq, (long long)NHq*Sq*Sq, (long long)Sq*Sq,
        pVthi, Sq, (long long)NHq*Dq*Sq, (long long)Dq*Sq,
        nullptr, pOhi, HIDq, (long long)Sq*HIDq, (long long)Dq,
        nullptr, nullptr, 0);

    // 9) h1 = hidden + O @ wo (1-term)
    wgemm<EPI_ADD,0><<<dim3(8,64,1), 128, SMEM_DYN>>>(HIDq,
        pOhi, HIDq, Z,Z, pWoThi, HIDq, Z,Z,
        pH1, nullptr, HIDq, Z,Z, hidden, nullptr, 0);

    // 10) rms2 (hi only), router, balance
    rms_k<<<Tq, 256>>>(pH1, ln2, pXp, pX2hi, nullptr);
    router_k<<<Tq/8, 256>>>(pXp, rwt, rb, pRW);
    balance_k<<<1, 1024>>>(pRW, out, (long long)Tq*HIDq, (long long)out_size);

    // 11) MoE gate: batched z=4, silu -> G4
    wgemm<EPI_SILU,1><<<dim3(16,64,4), 128, SMEM_DYN>>>(HIDq,
        pX2hi, HIDq, Z,Z,
        pGThi, HIDq, Z, (long long)IMq*HIDq,
        nullptr, pG4, 4*IMq, Z, (long long)IMq,
        nullptr, nullptr, 0);

    // 12) MoE up: batched z=4, fused * G4 * rw[:,e] -> GU4
    wgemm<EPI_MULSCALE,1><<<dim3(16,64,4), 128, SMEM_DYN>>>(HIDq,
        pX2hi, HIDq, Z,Z,
        pUThi, HIDq, Z, (long long)IMq*HIDq,
        nullptr, pGU4, 4*IMq, Z, (long long)IMq,
        pG4, pRW, Eq);

    // 13) MoE down: out = h1 + GU4 @ DT^T (K=8192)
    wgemm<EPI_ADD,0><<<dim3(8,64,1), 128, SMEM_DYN>>>(4*IMq,
        pGU4,  4*IMq, Z,Z,
        pDThi, 4*IMq, Z,Z,
        out, nullptr, HIDq, Z,Z, pH1, nullptr, 0);
}

// round 15
// speedup vs baseline: 1.0833x; 1.0212x over previous
#include <cuda_runtime.h>
#include <cuda_fp16.h>
#include <math.h>
#include <stdint.h>

#define Bq 4
#define Sq 2048
#define HIDq 1024
#define NHq 4
#define Dq 256
#define IMq 2048
#define Eq 4
#define Tq (Bq*Sq)

typedef __half h16;

// ---------------- scratch ----------------
__device__ h16 g_Xhi[Tq*HIDq], g_Xlo[Tq*HIDq];
__device__ h16 g_QKhi[2*Tq*HIDq], g_QKlo[2*Tq*HIDq];
__device__ float g_Vf[Tq*HIDq];
__device__ h16 g_Vthi[HIDq*Tq];
__device__ float g_S[67108864];
__device__ h16 g_Phi[67108864];
__device__ h16 g_Ohi[Tq*HIDq];
__device__ float g_H1[Tq*HIDq], g_Xp[Tq*HIDq];
__device__ h16 g_X2hi[Tq*HIDq];
__device__ h16 g_G4[(long long)Tq*IMq*Eq];
__device__ h16 g_GU4[(long long)Tq*IMq*Eq];
__device__ float g_RW[Tq*Eq];
__device__ h16 g_WqkThi[2*HIDq*HIDq], g_WqkTlo[2*HIDq*HIDq];
__device__ h16 g_WvThi[HIDq*HIDq];
__device__ h16 g_WoThi[HIDq*HIDq];
__device__ h16 g_GThi[Eq*IMq*HIDq];
__device__ h16 g_UThi[Eq*IMq*HIDq];
__device__ h16 g_DThi[(long long)Eq*HIDq*IMq];

// ---------------- helpers ----------------
__device__ __forceinline__ uint32_t smem_u32(const void* p) {
    uint32_t a;
    asm("{ .reg .u64 t; cvta.to.shared.u64 t, %1; cvt.u32.u64 %0, t; }" : "=r"(a) : "l"(p));
    return a;
}
__device__ __forceinline__ void hsplit(float v, h16& h, h16& l) {
    h = __float2half(v);
    l = __float2half(v - __half2float(h));
}
#define MMAH(c, a0,a1,a2,a3, b0,b1) \
    asm volatile("mma.sync.aligned.m16n8k16.row.col.f32.f16.f16.f32 " \
        "{%0,%1,%2,%3}, {%4,%5,%6,%7}, {%8,%9}, {%0,%1,%2,%3};" \
        : "+f"((c)[0]), "+f"((c)[1]), "+f"((c)[2]), "+f"((c)[3]) \
        : "r"(a0), "r"(a1), "r"(a2), "r"(a3), "r"(b0), "r"(b1))
#define LDSM4(r0,r1,r2,r3, addr) \
    asm volatile("ldmatrix.sync.aligned.m8n8.x4.shared.b16 {%0,%1,%2,%3}, [%4];" \
        : "=r"(r0), "=r"(r1), "=r"(r2), "=r"(r3) : "r"(addr))
#define CPA16(s, g) asm volatile("cp.async.cg.shared.global [%0], [%1], 16;" :: "r"(s), "l"(g))
#define CPA_COMMIT() asm volatile("cp.async.commit_group;")

// EPI codes.  SPLIT: 0 = fp32 C, 1 = h16 hi only, 2 = h16 hi+lo.
enum { EPI_NONE = 0, EPI_ELU1, EPI_SILU, EPI_ADD, EPI_MULSCALE };
#define TILE_B 10240
#define SMEM_DYN 81920

// ---------------- 1-term wide-warp GEMM: 128x128 tile, 4 warps of 64x64, 4 stages, 2 CTAs/SM ----------------
template<int EPI, int SPLIT>
__global__ __launch_bounds__(128, 2)
void wgemm(int K,
           const h16* __restrict__ A, int lda, long long sAb, long long sAh,
           const h16* __restrict__ B, int ldb, long long sBb, long long sBh,
           float* C, h16* Chi,
           int ldc, long long sCb, long long sCh,
           const void* __restrict__ Dp,
           const float* __restrict__ scale, int sstride) {
    constexpr int STAGES = 4;
    constexpr int STAGE_BYTES = 2 * TILE_B;

    extern __shared__ char smc[];
    const int t = threadIdx.x;
    const int lane = t & 31, wid = t >> 5;
    const int wm = wid & 1, wn = wid >> 1;      // 2x2 warps, each 64(M) x 64(N)
    const int zb = blockIdx.z >> 2, zh = blockIdx.z & 3;
    const int row0 = blockIdx.y * 128, col0 = blockIdx.x * 128;

    A += (long long)zb * sAb + (long long)zh * sAh;
    B += (long long)zb * sBb + (long long)zh * sBh;
    const long long coff = (long long)zb * sCb + (long long)zh * sCh;

    float c[4][8][4];
    #pragma unroll
    for (int i = 0; i < 4; i++)
        #pragma unroll
        for (int j = 0; j < 8; j++)
            #pragma unroll
            for (int k = 0; k < 4; k++) c[i][j][k] = 0.f;

    const int nkt = K >> 5;
    const uint32_t smu = smem_u32(smc);

    auto stage = [&](int kt, int buf) {
        const int k0 = kt << 5;
        const uint32_t sb = smu + buf * STAGE_BYTES;
        #pragma unroll
        for (int i = 0; i < 8; i++) {
            int chunk = t + (i << 7);
            int tile = chunk >> 9;
            int idx = chunk & 511;
            int row = idx >> 2;
            int q = idx & 3;
            const h16* g;
            if (tile == 0) g = A + (long long)(row0 + row) * lda + k0 + q * 8;
            else           g = B + (long long)(col0 + row) * ldb + k0 + q * 8;
            CPA16(sb + tile * TILE_B + row * 80 + q * 16, g);
        }
        CPA_COMMIT();
    };

    stage(0, 0);
    #pragma unroll
    for (int s = 1; s < STAGES - 1; s++)
        if (s < nkt) stage(s, s);

    for (int kt = 0; kt < nkt; kt++) {
        if (kt + STAGES - 1 < nkt)
            stage(kt + STAGES - 1, (kt + STAGES - 1) % STAGES);
        int rem = nkt - 1 - kt;
        if (rem > STAGES - 1) rem = STAGES - 1;
        if (rem >= 3)      asm volatile("cp.async.wait_group 3;");
        else if (rem == 2) asm volatile("cp.async.wait_group 2;");
        else if (rem == 1) asm volatile("cp.async.wait_group 1;");
        else               asm volatile("cp.async.wait_group 0;");
        __syncthreads();
        const uint32_t sA = smu + (kt % STAGES) * STAGE_BYTES;
        const uint32_t sB = sA + TILE_B;

        #pragma unroll
        for (int k16 = 0; k16 < 2; k16++) {
            const int kc = k16 << 4;
            uint32_t bh[8][2];
            const uint32_t brow = (uint32_t)(wn * 64 + (lane & 7) + ((lane & 16) ? 8 : 0));
            const uint32_t boff = brow * 80 + (uint32_t)(kc + ((lane & 8) ? 8 : 0)) * 2;
            #pragma unroll
            for (int np = 0; np < 4; np++)
                LDSM4(bh[2*np][0], bh[2*np][1], bh[2*np+1][0], bh[2*np+1][1],
                      sB + boff + np * 16 * 80);
            const uint32_t aoff = (uint32_t)(wm * 64 + (lane & 15)) * 80
                                + (uint32_t)(kc + ((lane >> 4) << 3)) * 2;
            #pragma unroll
            for (int mt = 0; mt < 4; mt++) {
                uint32_t a0, a1, a2, a3;
                LDSM4(a0, a1, a2, a3, sA + aoff + mt * 16 * 80);
                #pragma unroll
                for (int nt = 0; nt < 8; nt++)
                    MMAH(c[mt][nt], a0, a1, a2, a3, bh[nt][0], bh[nt][1]);
            }
        }
        __syncthreads();
    }

    #pragma unroll
    for (int mt = 0; mt < 4; mt++) {
        #pragma unroll
        for (int half = 0; half < 2; half++) {
            const long long r = row0 + wm * 64 + mt * 16 + (lane >> 2) + half * 8;
            float sc = 0.f;
            if (EPI == EPI_MULSCALE) sc = __ldg(scale + r * sstride + zh);
            #pragma unroll
            for (int nt = 0; nt < 8; nt++) {
                const long long gi = r * ldc + col0 + wn * 64 + nt * 8 + (lane & 3) * 2;
                float v0 = c[mt][nt][half * 2 + 0];
                float v1 = c[mt][nt][half * 2 + 1];
                if (EPI == EPI_SILU) {
                    v0 = v0 / (1.f + expf(-v0));
                    v1 = v1 / (1.f + expf(-v1));
                } else if (EPI == EPI_ADD) {
                    float2 d = *(const float2*)((const float*)Dp + coff + gi);
                    v0 += d.x; v1 += d.y;
                } else if (EPI == EPI_MULSCALE) {
                    __half2 d = *(const __half2*)((const h16*)Dp + coff + gi);
                    v0 *= __half2float(d.x) * sc;
                    v1 *= __half2float(d.y) * sc;
                }
                if (SPLIT == 1) {
                    __half2 hp; hp.x = __float2half(v0); hp.y = __float2half(v1);
                    *(__half2*)(Chi + coff + gi) = hp;
                } else {
                    *(float2*)(C + coff + gi) = make_float2(v0, v1);
                }
            }
        }
    }
}

// ---------------- 3-term wide-warp GEMM: 128x128 tile, 4 warps of 64x64, 2 stages ----------------
// D += Ah*Bh + Ah*Bl + Al*Bh
template<int EPI, int SPLIT>
__global__ __launch_bounds__(128, 2)
void wgemm3(int K,
            const h16* __restrict__ Ahi, const h16* __restrict__ Alo,
            int lda, long long sAb, long long sAh,
            const h16* __restrict__ Bhi, const h16* __restrict__ Blo,
            int ldb, long long sBb, long long sBh,
            float* C, h16* Chi, h16* Clo,
            int ldc, long long sCb, long long sCh) {
    constexpr int STAGE_BYTES = 4 * TILE_B;

    extern __shared__ char smc[];
    const int t = threadIdx.x;
    const int lane = t & 31, wid = t >> 5;
    const int wm = wid & 1, wn = wid >> 1;
    const int zb = blockIdx.z >> 2, zh = blockIdx.z & 3;
    const int row0 = blockIdx.y * 128, col0 = blockIdx.x * 128;

    Ahi += (long long)zb * sAb + (long long)zh * sAh;
    Alo += (long long)zb * sAb + (long long)zh * sAh;
    Bhi += (long long)zb * sBb + (long long)zh * sBh;
    Blo += (long long)zb * sBb + (long long)zh * sBh;
    const long long coff = (long long)zb * sCb + (long long)zh * sCh;

    float c[4][8][4];
    #pragma unroll
    for (int i = 0; i < 4; i++)
        #pragma unroll
        for (int j = 0; j < 8; j++)
            #pragma unroll
            for (int k = 0; k < 4; k++) c[i][j][k] = 0.f;

    const int nkt = K >> 5;
    const uint32_t smu = smem_u32(smc);

    // tiles: 0=Ah, 1=Bh, 2=Al, 3=Bl
    auto stage = [&](int kt, int buf) {
        const int k0 = kt << 5;
        const uint32_t sb = smu + buf * STAGE_BYTES;
        #pragma unroll
        for (int i = 0; i < 16; i++) {
            int chunk = t + (i << 7);
            int tile = chunk >> 9;
            int idx = chunk & 511;
            int row = idx >> 2;
            int q = idx & 3;
            const h16* g;
            if (tile == 0)      g = Ahi + (long long)(row0 + row) * lda + k0 + q * 8;
            else if (tile == 1) g = Bhi + (long long)(col0 + row) * ldb + k0 + q * 8;
            else if (tile == 2) g = Alo + (long long)(row0 + row) * lda + k0 + q * 8;
            else                g = Blo + (long long)(col0 + row) * ldb + k0 + q * 8;
            CPA16(sb + tile * TILE_B + row * 80 + q * 16, g);
        }
        CPA_COMMIT();
    };

    stage(0, 0);
    for (int kt = 0; kt < nkt; kt++) {
        if (kt + 1 < nkt) {
            stage(kt + 1, (kt + 1) & 1);
            asm volatile("cp.async.wait_group 1;");
        } else {
            asm volatile("cp.async.wait_group 0;");
        }
        __syncthreads();
        const uint32_t sb  = smu + (kt & 1) * STAGE_BYTES;
        const uint32_t sAh = sb;
        const uint32_t sBh = sb + TILE_B;
        const uint32_t sAl = sb + 2 * TILE_B;
        const uint32_t sBl = sb + 3 * TILE_B;

        #pragma unroll
        for (int k16 = 0; k16 < 2; k16++) {
            const int kc = k16 << 4;
            uint32_t bh[8][2], bl[8][2];
            const uint32_t brow = (uint32_t)(wn * 64 + (lane & 7) + ((lane & 16) ? 8 : 0));
            const uint32_t boff = brow * 80 + (uint32_t)(kc + ((lane & 8) ? 8 : 0)) * 2;
            #pragma unroll
            for (int np = 0; np < 4; np++) {
                LDSM4(bh[2*np][0], bh[2*np][1], bh[2*np+1][0], bh[2*np+1][1],
                      sBh + boff + np * 16 * 80);
                LDSM4(bl[2*np][0], bl[2*np][1], bl[2*np+1][0], bl[2*np+1][1],
                      sBl + boff + np * 16 * 80);
            }
            const uint32_t aoff = (uint32_t)(wm * 64 + (lane & 15)) * 80
                                + (uint32_t)(kc + ((lane >> 4) << 3)) * 2;
            #pragma unroll
            for (int mt = 0; mt < 4; mt++) {
                uint32_t ah0, ah1, ah2, ah3, al0, al1, al2, al3;
                LDSM4(ah0, ah1, ah2, ah3, sAh + aoff + mt * 16 * 80);
                LDSM4(al0, al1, al2, al3, sAl + aoff + mt * 16 * 80);
                #pragma unroll
                for (int nt = 0; nt < 8; nt++) {
                    MMAH(c[mt][nt], ah0, ah1, ah2, ah3, bh[nt][0], bh[nt][1]);
                    MMAH(c[mt][nt], ah0, ah1, ah2, ah3, bl[nt][0], bl[nt][1]);
                    MMAH(c[mt][nt], al0, al1, al2, al3, bh[nt][0], bh[nt][1]);
                }
            }
        }
        __syncthreads();
    }

    #pragma unroll
    for (int mt = 0; mt < 4; mt++) {
        #pragma unroll
        for (int half = 0; half < 2; half++) {
            const long long r = row0 + wm * 64 + mt * 16 + (lane >> 2) + half * 8;
            #pragma unroll
            for (int nt = 0; nt < 8; nt++) {
                const long long gi = r * ldc + col0 + wn * 64 + nt * 8 + (lane & 3) * 2;
                float v0 = c[mt][nt][half * 2 + 0];
                float v1 = c[mt][nt][half * 2 + 1];
                if (EPI == EPI_ELU1) {
                    v0 = (v0 >= 0.f) ? v0 + 1.f : expf(v0);
                    v1 = (v1 >= 0.f) ? v1 + 1.f : expf(v1);
                }
                if (SPLIT == 2) {
                    h16 h0, l0, h1, l1;
                    hsplit(v0, h0, l0); hsplit(v1, h1, l1);
                    __half2 hp; hp.x = h0; hp.y = h1;
                    __half2 lp; lp.x = l0; lp.y = l1;
                    *(__half2*)(Chi + coff + gi) = hp;
                    *(__half2*)(Clo + coff + gi) = lp;
                } else {
                    *(float2*)(C + coff + gi) = make_float2(v0, v1);
                }
            }
        }
    }
}

// ---------------- reductions ----------------
__device__ __forceinline__ float blk_sum(float v, float* sh) {
    __syncthreads();
    int t = threadIdx.x, lane = t & 31, w = t >> 5;
    #pragma unroll
    for (int o = 16; o; o >>= 1) v += __shfl_down_sync(0xffffffffu, v, o);
    if (lane == 0) sh[w] = v;
    __syncthreads();
    float r = (t < (int)(blockDim.x >> 5)) ? sh[t] : 0.f;
    if (w == 0) {
        #pragma unroll
        for (int o = 16; o; o >>= 1) r += __shfl_down_sync(0xffffffffu, r, o);
        if (t == 0) sh[0] = r;
    }
    __syncthreads();
    return sh[0];
}
__device__ __forceinline__ float blk_max(float v, float* sh) {
    __syncthreads();
    int t = threadIdx.x, lane = t & 31, w = t >> 5;
    #pragma unroll
    for (int o = 16; o; o >>= 1) v = fmaxf(v, __shfl_down_sync(0xffffffffu, v, o));
    if (lane == 0) sh[w] = v;
    __syncthreads();
    float r = (t < (int)(blockDim.x >> 5)) ? sh[t] : -1e30f;
    if (w == 0) {
        #pragma unroll
        for (int o = 16; o; o >>= 1) r = fmaxf(r, __shfl_down_sync(0xffffffffu, r, o));
        if (t == 0) sh[0] = r;
    }
    __syncthreads();
    return sh[0];
}

// ---------------- RMSNorm + fp16 split (lo optional) ----------------
__global__ void rms_k(const float* __restrict__ x, const float* __restrict__ w,
                      float* __restrict__ y, h16* __restrict__ yhi, h16* __restrict__ ylo) {
    __shared__ float sh[32];
    long long row = blockIdx.x;
    const float4 xv = *(const float4*)(x + row * HIDq + threadIdx.x * 4);
    float ss = xv.x*xv.x + xv.y*xv.y + xv.z*xv.z + xv.w*xv.w;
    ss = blk_sum(ss, sh);
    float inv = rsqrtf(ss * (1.0f / HIDq) + 1e-6f);
    const float4 wv = *(const float4*)(w + threadIdx.x * 4);
    float v[4] = { xv.x*inv*wv.x, xv.y*inv*wv.y, xv.z*inv*wv.z, xv.w*inv*wv.w };
    float4 p;
    h16 hb[4], lb[4];
    #pragma unroll
    for (int i = 0; i < 4; i++) {
        ((float*)&p)[i] = v[i];
        hsplit(v[i], hb[i], lb[i]);
    }
    *(float4*)(y + row * HIDq + threadIdx.x * 4) = p;
    *(uint2*)(yhi + row * HIDq + threadIdx.x * 4) = *(uint2*)hb;
    if (ylo)
        *(uint2*)(ylo + row * HIDq + threadIdx.x * 4) = *(uint2*)lb;
}

// ---------------- softmax (hi only) ----------------
__global__ void softmax_k(const float* __restrict__ s, h16* __restrict__ phi) {
    __shared__ float sh[32];
    long long base = (long long)blockIdx.x * Sq;
    int t = threadIdx.x;
    float v[8]; float mx = -1e30f;
    #pragma unroll
    for (int i = 0; i < 8; i++) { v[i] = s[base + t + 256*i]; mx = fmaxf(mx, v[i]); }
    mx = blk_max(mx, sh);
    float sum = 0.f;
    #pragma unroll
    for (int i = 0; i < 8; i++) { v[i] = expf(v[i] - mx); sum += v[i]; }
    sum = blk_sum(sum, sh);
    float inv = 1.0f / sum;
    #pragma unroll
    for (int i = 0; i < 8; i++)
        phi[base + t + 256*i] = __float2half(v[i] * inv);
}

// ---------------- transpose + fp16 split (lo optional) ----------------
__global__ void tsplit_k(const float* __restrict__ in, h16* __restrict__ ohi,
                         h16* __restrict__ olo, int ldin, int ldout,
                         long long sIb, long long sIh, long long sOb, long long sOh) {
    __shared__ float tile[32][33];
    int z = blockIdx.z, zb = z >> 2, zh = z & 3;
    in  += (long long)zb * sIb + (long long)zh * sIh;
    ohi += (long long)zb * sOb + (long long)zh * sOh;
    if (olo) olo += (long long)zb * sOb + (long long)zh * sOh;
    int r0 = blockIdx.y * 32, c0 = blockIdx.x * 32;
    int tx = threadIdx.x, ty = threadIdx.y;
    #pragma unroll
    for (int k = 0; k < 4; k++)
        tile[ty + 8*k][tx] = in[(long long)(r0 + ty + 8*k) * ldin + c0 + tx];
    __syncthreads();
    #pragma unroll
    for (int k = 0; k < 4; k++) {
        float v = tile[tx][ty + 8*k];
        long long oi = (long long)(c0 + ty + 8*k) * ldout + r0 + tx;
        h16 h, l;
        hsplit(v, h, l);
        ohi[oi] = h;
        if (olo) olo[oi] = l;
    }
}

// ---------------- router ----------------
__global__ void router_k(const float* __restrict__ x2, const float* __restrict__ rwt,
                         const float* __restrict__ rb, float* __restrict__ rw) {
    int warp = threadIdx.x >> 5, lane = threadIdx.x & 31;
    long long token = (long long)blockIdx.x * (blockDim.x >> 5) + warp;
    const float* xr = x2 + token * HIDq;
    float a0=0.f, a1=0.f, a2=0.f, a3=0.f;
    for (int k = lane; k < HIDq; k += 32) {
        float xv = xr[k];
        float4 w4 = *(const float4*)(rwt + (long long)k * Eq);
        a0 = fmaf(xv, w4.x, a0); a1 = fmaf(xv, w4.y, a1);
        a2 = fmaf(xv, w4.z, a2); a3 = fmaf(xv, w4.w, a3);
    }
    #pragma unroll
    for (int o = 16; o; o >>= 1) {
        a0 += __shfl_down_sync(0xffffffffu, a0, o);
        a1 += __shfl_down_sync(0xffffffffu, a1, o);
        a2 += __shfl_down_sync(0xffffffffu, a2, o);
        a3 += __shfl_down_sync(0xffffffffu, a3, o);
    }
    if (lane == 0) {
        float l0=a0+rb[0], l1=a1+rb[1], l2=a2+rb[2], l3=a3+rb[3];
        float m = fmaxf(fmaxf(l0,l1), fmaxf(l2,l3));
        float e0=expf(l0-m), e1=expf(l1-m), e2=expf(l2-m), e3=expf(l3-m);
        float inv = 1.0f / (e0+e1+e2+e3);
        float4 o4; o4.x=e0*inv; o4.y=e1*inv; o4.z=e2*inv; o4.w=e3*inv;
        *(float4*)(rw + token * Eq) = o4;
    }
}

// ---------------- balance loss ----------------
__global__ void balance_k(const float* __restrict__ rw, float* __restrict__ out,
                          long long tail_begin, long long out_size) {
    __shared__ float red[1024];
    int t = threadIdx.x;
    float s = 0.f;
    for (int idx = t; idx < Sq * Eq; idx += 1024) {
        int srow = idx / Eq, e = idx % Eq;
        float m = 0.f;
        #pragma unroll
        for (int b = 0; b < Bq; b++) m += rw[((long long)b * Sq + srow) * Eq + e];
        m *= (1.0f / Bq);
        float d = m - 1.0f / Eq;
        s += d * d;
    }
    red[t] = s;
    __syncthreads();
    for (int o = 512; o; o >>= 1) { if (t < o) red[t] += red[t + o]; __syncthreads(); }
    if (t == 0) {
        float loss = red[0] / ((float)Sq * Eq) * 0.01f;
        for (long long i = tail_begin; i < out_size; i++) out[i] = loss;
    }
}

// ---------------- host ----------------
#define SYMF(p, s) float* p; cudaGetSymbolAddress((void**)&p, s)
#define SYMH(p, s) h16* p; cudaGetSymbolAddress((void**)&p, s)

extern "C" void kernel_launch(void* const* d_in, const int* in_sizes, int n_in,
                              void* d_out, int out_size) {
    const float* hidden = (const float*)d_in[0];
    const float* ln1 = (const float*)d_in[1];
    const float* wq = (const float*)d_in[2];
    const float* wk = (const float*)d_in[3];
    const float* wv = (const float*)d_in[4];
    const float* wo = (const float*)d_in[5];
    const float* ln2 = (const float*)d_in[6];
    const float* rwt = (const float*)d_in[7];
    const float* rb = (const float*)d_in[8];
    const float* gw = (const float*)d_in[9];
    const float* uw = (const float*)d_in[10];
    const float* dwn = (const float*)d_in[11];
    float* out = (float*)d_out;

    SYMH(pXhi, g_Xhi); SYMH(pXlo, g_Xlo);
    SYMH(pQKhi, g_QKhi); SYMH(pQKlo, g_QKlo);
    SYMF(pVf, g_Vf);
    SYMH(pVthi, g_Vthi);
    SYMF(pS, g_S); SYMH(pPhi, g_Phi);
    SYMH(pOhi, g_Ohi); SYMF(pH1, g_H1); SYMF(pXp, g_Xp);
    SYMH(pX2hi, g_X2hi);
    SYMH(pG4, g_G4); SYMH(pGU4, g_GU4); SYMF(pRW, g_RW);
    SYMH(pWqkThi, g_WqkThi); SYMH(pWqkTlo, g_WqkTlo);
    SYMH(pWvThi, g_WvThi);
    SYMH(pWoThi, g_WoThi);
    SYMH(pGThi, g_GThi);
    SYMH(pUThi, g_UThi);
    SYMH(pDThi, g_DThi);

    cudaFuncSetAttribute(wgemm3<EPI_ELU1,2>,    cudaFuncAttributeMaxDynamicSharedMemorySize, SMEM_DYN);
    cudaFuncSetAttribute(wgemm3<EPI_NONE,0>,    cudaFuncAttributeMaxDynamicSharedMemorySize, SMEM_DYN);
    cudaFuncSetAttribute(wgemm<EPI_NONE,0>,     cudaFuncAttributeMaxDynamicSharedMemorySize, SMEM_DYN);
    cudaFuncSetAttribute(wgemm<EPI_NONE,1>,     cudaFuncAttributeMaxDynamicSharedMemorySize, SMEM_DYN);
    cudaFuncSetAttribute(wgemm<EPI_ADD,0>,      cudaFuncAttributeMaxDynamicSharedMemorySize, SMEM_DYN);
    cudaFuncSetAttribute(wgemm<EPI_SILU,1>,     cudaFuncAttributeMaxDynamicSharedMemorySize, SMEM_DYN);
    cudaFuncSetAttribute(wgemm<EPI_MULSCALE,1>, cudaFuncAttributeMaxDynamicSharedMemorySize, SMEM_DYN);

    // one-time stream/event setup (resources only; every call launches identical work)
    static cudaStream_t sB = 0;
    static cudaEvent_t evX = 0, evVt = 0, evWoT = 0, evMoEW = 0, evRW = 0, evX2 = 0;
    if (!sB) {
        cudaStreamCreateWithFlags(&sB, cudaStreamNonBlocking);
        cudaEventCreateWithFlags(&evX,    cudaEventDisableTiming);
        cudaEventCreateWithFlags(&evVt,   cudaEventDisableTiming);
        cudaEventCreateWithFlags(&evWoT,  cudaEventDisableTiming);
        cudaEventCreateWithFlags(&evMoEW, cudaEventDisableTiming);
        cudaEventCreateWithFlags(&evRW,   cudaEventDisableTiming);
        cudaEventCreateWithFlags(&evX2,   cudaEventDisableTiming);
    }

    const long long Z = 0;
    const dim3 tb(32, 8);
    const long long TH = (long long)Tq * HIDq;
    const long long HH = (long long)HIDq * HIDq;
    cudaStream_t D = 0;

    // ---- main stream: rms1 (produces X), fork point ----
    rms_k<<<Tq, 256, 0, D>>>(hidden, ln1, pXp, pXhi, pXlo);
    cudaEventRecord(evX, D);

    // ---- side stream: V chain + remaining weight preps ----
    cudaStreamWaitEvent(sB, evX, 0);
    tsplit_k<<<dim3(32,32,1), tb, 0, sB>>>(wv, pWvThi, nullptr, HIDq, HIDq, Z,Z,Z,Z);
    wgemm<EPI_NONE,0><<<dim3(8,64,1), 128, SMEM_DYN, sB>>>(HIDq,
        pXhi, HIDq, Z,Z, pWvThi, HIDq, Z,Z,
        pVf, nullptr, HIDq, Z,Z, nullptr, nullptr, 0);
    tsplit_k<<<dim3(8,64,16), tb, 0, sB>>>(pVf, pVthi, nullptr, HIDq, Sq,
        (long long)Sq*HIDq, (long long)Dq,
        (long long)NHq*Dq*Sq, (long long)Dq*Sq);
    cudaEventRecord(evVt, sB);
    tsplit_k<<<dim3(32,32,1), tb, 0, sB>>>(wo, pWoThi, nullptr, HIDq, HIDq, Z,Z,Z,Z);
    cudaEventRecord(evWoT, sB);
    tsplit_k<<<dim3(64,32,4), tb, 0, sB>>>(gw, pGThi, nullptr, IMq, HIDq, Z,(long long)HIDq*IMq, Z,(long long)IMq*HIDq);
    tsplit_k<<<dim3(64,32,4), tb, 0, sB>>>(uw, pUThi, nullptr, IMq, HIDq, Z,(long long)HIDq*IMq, Z,(long long)IMq*HIDq);
    tsplit_k<<<dim3(32,64,4), tb, 0, sB>>>(dwn, pDThi, nullptr, HIDq, 4*IMq, Z,(long long)IMq*HIDq, Z,(long long)IMq);
    cudaEventRecord(evMoEW, sB);

    // ---- main stream: QK weights, QK proj, scores, softmax ----
    tsplit_k<<<dim3(32,32,1), tb, 0, D>>>(wq, pWqkThi,      pWqkTlo,      HIDq, HIDq, Z,Z,Z,Z);
    tsplit_k<<<dim3(32,32,1), tb, 0, D>>>(wk, pWqkThi + HH, pWqkTlo + HH, HIDq, HIDq, Z,Z,Z,Z);
    wgemm3<EPI_ELU1,2><<<dim3(8,64,2), 128, SMEM_DYN, D>>>(HIDq,
        pXhi, pXlo, HIDq, Z,Z,
        pWqkThi, pWqkTlo, HIDq, Z, HH,
        nullptr, pQKhi, pQKlo, HIDq, Z, TH);
    wgemm3<EPI_NONE,0><<<dim3(16,16,16), 128, SMEM_DYN, D>>>(Dq,
        pQKhi,      pQKlo,      HIDq, (long long)Sq*HIDq, (long long)Dq,
        pQKhi + TH, pQKlo + TH, HIDq, (long long)Sq*HIDq, (long long)Dq,
        pS, nullptr, nullptr, Sq, (long long)NHq*Sq*Sq, (long long)Sq*Sq);
    softmax_k<<<Bq*NHq*Sq, 256, 0, D>>>(pS, pPhi);

    // ---- PV (needs Vt), wo (needs WoT), rms2 ----
    cudaStreamWaitEvent(D, evVt, 0);
    wgemm<EPI_NONE,1><<<dim3(2,16,16), 128, SMEM_DYN, D>>>(Sq,
        pPhi,  Sq, (long long)NHq*Sq*Sq, (long long)Sq*Sq,
        pVthi, Sq, (long long)NHq*Dq*Sq, (long long)Dq*Sq,
        nullptr, pOhi, HIDq, (long long)Sq*HIDq, (long long)Dq,
        nullptr, nullptr, 0);
    cudaStreamWaitEvent(D, evWoT, 0);
    wgemm<EPI_ADD,0><<<dim3(8,64,1), 128, SMEM_DYN, D>>>(HIDq,
        pOhi, HIDq, Z,Z, pWoThi, HIDq, Z,Z,
        pH1, nullptr, HIDq, Z,Z, hidden, nullptr, 0);
    rms_k<<<Tq, 256, 0, D>>>(pH1, ln2, pXp, pX2hi, nullptr);
    cudaEventRecord(evX2, D);

    // ---- side stream: router + balance (after X2) ----
    cudaStreamWaitEvent(sB, evX2, 0);
    router_k<<<Tq/8, 256, 0, sB>>>(pXp, rwt, rb, pRW);
    balance_k<<<1, 1024, 0, sB>>>(pRW, out, TH, (long long)out_size);
    cudaEventRecord(evRW, sB);

    // ---- main stream: MoE (gate needs MoE weights; up needs RW) ----
    cudaStreamWaitEvent(D, evMoEW, 0);
    wgemm<EPI_SILU,1><<<dim3(16,64,4), 128, SMEM_DYN, D>>>(HIDq,
        pX2hi, HIDq, Z,Z,
        pGThi, HIDq, Z, (long long)IMq*HIDq,
        nullptr, pG4, 4*IMq, Z, (long long)IMq,
        nullptr, nullptr, 0);
    cudaStreamWaitEvent(D, evRW, 0);
    wgemm<EPI_MULSCALE,1><<<dim3(16,64,4), 128, SMEM_DYN, D>>>(HIDq,
        pX2hi, HIDq, Z,Z,
        pUThi, HIDq, Z, (long long)IMq*HIDq,
        nullptr, pGU4, 4*IMq, Z, (long long)IMq,
        pG4, pRW, Eq);
    wgemm<EPI_ADD,0><<<dim3(8,64,1), 128, SMEM_DYN, D>>>(4*IMq,
        pGU4,  4*IMq, Z,Z,
        pDThi, 4*IMq, Z,Z,
        out, nullptr, HIDq, Z,Z, pH1, nullptr, 0);
}